// round 14
// baseline (speedup 1.0000x reference)
#include <cuda_runtime.h>
#include <cstdint>

#define BATCH  32
#define HW     3136
#define C      256
#define CR     64
#define PPC    16            // pixels per chunk
#define CHUNKS 196           // HW / PPC
#define NG     32            // channel groups of 8 floats
#define BPG    8             // batches per group
#define GROUPS 4
#define GAPB   (CHUNKS * BPG)   // 1568 gap blocks per stage

// Scratch (allocation-free per harness rules)
__device__ float g_partial[BATCH * CHUNKS * C];
__device__ float g_gate[BATCH * C];
__device__ int   g_count[BATCH];     // zero-init; fc resets after consuming

__device__ __forceinline__ void ld256(const float* p, uint32_t* u) {
    asm volatile("ld.global.nc.v8.b32 {%0,%1,%2,%3,%4,%5,%6,%7}, [%8];"
                 : "=r"(u[0]), "=r"(u[1]), "=r"(u[2]), "=r"(u[3]),
                   "=r"(u[4]), "=r"(u[5]), "=r"(u[6]), "=r"(u[7])
                 : "l"(p));
}
__device__ __forceinline__ void st256(float* p, const uint32_t* u) {
    asm volatile("st.global.v8.b32 [%0], {%1,%2,%3,%4,%5,%6,%7,%8};"
                 :: "l"(p),
                    "r"(u[0]), "r"(u[1]), "r"(u[2]), "r"(u[3]),
                    "r"(u[4]), "r"(u[5]), "r"(u[6]), "r"(u[7]));
}

// ---- role bodies -----------------------------------------------------------

__device__ void do_gap(const float* __restrict__ x, int chunk, int b) {
    const int tid = threadIdx.x;
    const int c8  = tid & (NG - 1);
    const int pr  = tid >> 5;

    const float* xp = x + ((size_t)(b * HW + chunk * PPC + pr)) * C + c8 * 8;

    uint32_t u0[8], u1[8];
    ld256(xp,                 u0);
    ld256(xp + (size_t)8 * C, u1);

    __shared__ float red[8 * C];
    float* rp = &red[pr * C + c8 * 8];
#pragma unroll
    for (int k = 0; k < 8; ++k) {
        rp[k] = __uint_as_float(u0[k]) + __uint_as_float(u1[k]);
    }
    __syncthreads();

    float p0 = 0.0f;
#pragma unroll
    for (int g = 0; g < 8; ++g) p0 += red[g * C + tid];
    g_partial[(b * CHUNKS + chunk) * C + tid] = p0;

    __threadfence();                 // publish partial before counter bump
    __syncthreads();
    if (tid == 0) atomicAdd(&g_count[b], 1);
}

__device__ void do_mul(const float* __restrict__ x, float* __restrict__ out,
                       int chunk, int b) {
    const int tid = threadIdx.x;
    const int c8  = tid & (NG - 1);
    const int pr  = tid >> 5;

    float g[8];
    {
        const float4 ga = __ldg(&((const float4*)g_gate)[b * (C / 4) + c8 * 2]);
        const float4 gb = __ldg(&((const float4*)g_gate)[b * (C / 4) + c8 * 2 + 1]);
        g[0] = ga.x; g[1] = ga.y; g[2] = ga.z; g[3] = ga.w;
        g[4] = gb.x; g[5] = gb.y; g[6] = gb.z; g[7] = gb.w;
    }

    const size_t off = ((size_t)(b * HW + chunk * PPC + pr)) * C + c8 * 8;
    const float* xp = x + off;
    float*       op = out + off;

    uint32_t u0[8], u1[8];
    ld256(xp,                 u0);
    ld256(xp + (size_t)8 * C, u1);
#pragma unroll
    for (int k = 0; k < 8; ++k) {
        u0[k] = __float_as_uint(__uint_as_float(u0[k]) * g[k]);
        u1[k] = __float_as_uint(__uint_as_float(u1[k]) * g[k]);
    }
    st256(op,                 u0);
    st256(op + (size_t)8 * C, u1);
}

__device__ void do_fc(const float* __restrict__ w1, const float* __restrict__ w2,
                      int b) {
    const int t = threadIdx.x;

    // wait for this batch's 196 gap blocks (same launch, dispatched earlier)
    if (t == 0) {
        while (atomicAdd(&g_count[b], 0) < CHUNKS) { __nanosleep(64); }
    }
    __syncthreads();
    __threadfence();

    __shared__ float s[C];
    __shared__ float h[CR];

    float a[8];
#pragma unroll
    for (int i = 0; i < 8; ++i) a[i] = 0.0f;

    const float* pp = &g_partial[(size_t)b * CHUNKS * C + t];
    int k = 0;
#pragma unroll 1
    for (; k + 8 <= CHUNKS; k += 8) {
#pragma unroll
        for (int i = 0; i < 8; ++i) a[i] += __ldcg(&pp[(size_t)(k + i) * C]);
    }
#pragma unroll
    for (int i = 0; i < 4; ++i) a[i] += __ldcg(&pp[(size_t)(k + i) * C]);  // 196=24*8+4
#pragma unroll
    for (int i = 4; i > 0; i >>= 1) {
#pragma unroll
        for (int j = 0; j < i; ++j) a[j] += a[j + i];
    }
    s[t] = a[0] * (1.0f / (float)HW);
    __syncthreads();

    if (t < CR) {
        float acc = 0.0f;
#pragma unroll 8
        for (int c = 0; c < C; ++c) acc += s[c] * w1[c * CR + t];
        h[t] = fminf(fmaxf(acc, 0.0f), 6.0f);
    }
    __syncthreads();

    float acc = 0.0f;
#pragma unroll
    for (int r = 0; r < CR; ++r) acc += h[r] * w2[r * C + t];
    g_gate[b * C + t] = fminf(fmaxf(acc + 3.0f, 0.0f), 6.0f) * (1.0f / 6.0f);

    __syncthreads();
    if (t == 0) g_count[b] = 0;      // reset for next graph replay
}

// ---------------------------------------------------------------------------
// stage_kernel: block roles by index — [0,n_mul): mul(b0_mul group),
// [n_mul, n_mul+n_gap): gap(b0_gap group), rest: fc spin-blocks (1/batch).
// Dispatch order guarantees fc blocks start after all gap blocks.
// ---------------------------------------------------------------------------
__global__ __launch_bounds__(256, 6) void stage_kernel(
    const float* __restrict__ x,
    const float* __restrict__ w1,
    const float* __restrict__ w2,
    float*       __restrict__ out,
    int n_mul, int n_gap, int b0_mul, int b0_gap)
{
    const int bid = blockIdx.x;
    if (bid < n_mul) {
        do_mul(x, out, bid % CHUNKS, b0_mul + bid / CHUNKS);
    } else if (bid < n_mul + n_gap) {
        const int id = bid - n_mul;
        do_gap(x, id % CHUNKS, b0_gap + id / CHUNKS);
    } else {
        do_fc(w1, w2, b0_gap + (bid - n_mul - n_gap));
    }
}

extern "C" void kernel_launch(void* const* d_in, const int* in_sizes, int n_in,
                              void* d_out, int out_size) {
    const float* x  = (const float*)d_in[0];
    const float* w1 = (const float*)d_in[1];
    const float* w2 = (const float*)d_in[2];
    float* out      = (float*)d_out;

    // stage 0: gap(g0) + fc(g0)
    stage_kernel<<<GAPB + BPG, 256>>>(x, w1, w2, out, 0, GAPB, 0, 0);
    // stages 1..GROUPS-1: mul(g-1) + gap(g) + fc(g)
    for (int g = 1; g < GROUPS; ++g) {
        stage_kernel<<<GAPB + GAPB + BPG, 256>>>(
            x, w1, w2, out, GAPB, GAPB, (g - 1) * BPG, g * BPG);
    }
    // final: mul(last group)
    stage_kernel<<<GAPB, 256>>>(x, w1, w2, out,
                                GAPB, 0, (GROUPS - 1) * BPG, 0);
}

// round 15
// speedup vs baseline: 1.8735x; 1.8735x over previous
#include <cuda_runtime.h>
#include <cstdint>

#define BATCH   32
#define HW      3136
#define C       256
#define C4      64           // C/4
#define CR      64
#define PPC_G   16           // gap pixels per chunk
#define CH_G    196          // HW / PPC_G
#define PPC_M   64           // mul pixels per chunk (R2 geometry)
#define CH_M    49           // HW / PPC_M
#define NG      32           // channel groups of 8 floats

// Scratch (allocation-free per harness rules)
__device__ float g_partial[BATCH * CH_G * C];
__device__ float g_gate[BATCH * C];

// 256-bit load, pin line in L2 (evict_last) — R9's fastest gap load
__device__ __forceinline__ void ld256_evict_last(const float* p, uint32_t* u) {
    asm volatile("ld.global.nc.L2::evict_last.v8.b32 {%0,%1,%2,%3,%4,%5,%6,%7}, [%8];"
                 : "=r"(u[0]), "=r"(u[1]), "=r"(u[2]), "=r"(u[3]),
                   "=r"(u[4]), "=r"(u[5]), "=r"(u[6]), "=r"(u[7])
                 : "l"(p));
}

// ---------------------------------------------------------------------------
// gap_kernel: R9's exact fastest configuration (18.9us, 5.68 TB/s).
// grid = (CH_G, BATCH) = 6272 blocks, 256 threads. evict_last v8 loads;
// plain partial store (keeps partials L2-resident for fc).
// ---------------------------------------------------------------------------
__global__ __launch_bounds__(256) void gap_kernel(const float* __restrict__ x)
{
    const int chunk = blockIdx.x;
    const int b     = blockIdx.y;
    const int tid   = threadIdx.x;
    const int c8    = tid & (NG - 1);
    const int pr    = tid >> 5;

    const float* xp = x + ((size_t)(b * HW + chunk * PPC_G + pr)) * C + c8 * 8;

    uint32_t u0[8], u1[8];
    ld256_evict_last(xp,                 u0);
    ld256_evict_last(xp + (size_t)8 * C, u1);

    __shared__ float red[8 * C];       // 8KB
    float* rp = &red[pr * C + c8 * 8];
#pragma unroll
    for (int k = 0; k < 8; ++k) {
        rp[k] = __uint_as_float(u0[k]) + __uint_as_float(u1[k]);
    }
    __syncthreads();

    float p0 = 0.0f;
#pragma unroll
    for (int g = 0; g < 8; ++g) {
        p0 += red[g * C + tid];
    }
    g_partial[(b * CH_G + chunk) * C + tid] = p0;
}

// ---------------------------------------------------------------------------
// fc_kernel: 32 blocks x 256 threads. 4-way accumulate over 196 partials
// (L2-hot thanks to plain stores in gap), then squeeze->relu6->excite->
// hsigmoid -> gate.
// ---------------------------------------------------------------------------
__global__ __launch_bounds__(256) void fc_kernel(const float* __restrict__ w1,
                                                 const float* __restrict__ w2)
{
    const int b = blockIdx.x;
    const int t = threadIdx.x;

    __shared__ float s[C];
    __shared__ float h[CR];

    float s0 = 0.f, s1 = 0.f, s2 = 0.f, s3 = 0.f;
#pragma unroll
    for (int k = 0; k < CH_G; k += 4) {
        s0 += __ldg(&g_partial[(b * CH_G + k + 0) * C + t]);
        s1 += __ldg(&g_partial[(b * CH_G + k + 1) * C + t]);
        s2 += __ldg(&g_partial[(b * CH_G + k + 2) * C + t]);
        s3 += __ldg(&g_partial[(b * CH_G + k + 3) * C + t]);
    }
    s[t] = ((s0 + s1) + (s2 + s3)) * (1.0f / (float)HW);
    __syncthreads();

    if (t < CR) {
        float acc = 0.0f;
#pragma unroll 8
        for (int c = 0; c < C; ++c) {
            acc += s[c] * w1[c * CR + t];
        }
        h[t] = fminf(fmaxf(acc, 0.0f), 6.0f);
    }
    __syncthreads();

    float acc = 0.0f;
#pragma unroll
    for (int r = 0; r < CR; ++r) {
        acc += h[r] * w2[r * C + t];
    }
    g_gate[b * C + t] = fminf(fmaxf(acc + 3.0f, 0.0f), 6.0f) * (1.0f / 6.0f);
}

// ---------------------------------------------------------------------------
// mul_kernel: R2's exact configuration — the best measured mul (70.6us total).
// grid = (CH_M, BATCH) = 1568 blocks, 256 threads. Each thread owns one
// channel group (gate in register) and 64 pixels: 16 interleaved
// load -> multiply -> __stcs iterations. Batch order REVERSED so the first
// reads hit the most-recently-streamed (MRU) end of whatever x survives
// in L2 from gap_kernel.
// ---------------------------------------------------------------------------
__global__ __launch_bounds__(256) void mul_kernel(const float4* __restrict__ x4,
                                                  float4* __restrict__ out4)
{
    const int chunk = blockIdx.x;
    const int b     = (BATCH - 1) - blockIdx.y;   // reversed batch order
    const int tid   = threadIdx.x;
    const int c4    = tid & (C4 - 1);
    const int pr    = tid >> 6;

    const float4 gv = __ldg(&((const float4*)g_gate)[b * C4 + c4]);

    const size_t base = ((size_t)(b * HW + chunk * PPC_M + pr)) * C4 + c4;

#pragma unroll
    for (int p = 0; p < PPC_M / 4; ++p) {        // 16 iterations
        size_t idx = base + (size_t)p * 4 * C4;
        float4 v = x4[idx];
        v.x *= gv.x; v.y *= gv.y; v.z *= gv.z; v.w *= gv.w;
        __stcs(&out4[idx], v);
    }
}

extern "C" void kernel_launch(void* const* d_in, const int* in_sizes, int n_in,
                              void* d_out, int out_size) {
    const float* x  = (const float*)d_in[0];
    const float* w1 = (const float*)d_in[1];
    const float* w2 = (const float*)d_in[2];
    float* out      = (float*)d_out;

    dim3 ggrid(CH_G, BATCH);
    gap_kernel<<<ggrid, 256>>>(x);
    fc_kernel<<<BATCH, 256>>>(w1, w2);
    dim3 mgrid(CH_M, BATCH);
    mul_kernel<<<mgrid, 256>>>((const float4*)x, (float4*)out);
}